// round 1
// baseline (speedup 1.0000x reference)
#include <cuda_runtime.h>

#define N_NODES 100000
#define N_EDGES 3200000
#define F_IN    256
#define F_OUT   128

// ---- device scratch (no allocations allowed) ----
__device__ __align__(16) float g_h[N_NODES * F_OUT];     // 51.2 MB, projected features
__device__ int   g_csr_col[N_EDGES];
__device__ float g_csr_val[N_EDGES];
__device__ int   g_deg[N_NODES];
__device__ int   g_offs[N_NODES + 1];
__device__ int   g_cursor[N_NODES];

// ---------------------------------------------------------------------------
// CSR build: degree count -> single-block scan -> scatter
// ---------------------------------------------------------------------------
__global__ void k_zero_deg() {
    int i = blockIdx.x * blockDim.x + threadIdx.x;
    if (i < N_NODES) g_deg[i] = 0;
}

__global__ void k_degrees(const int* __restrict__ rows) {
    int e = blockIdx.x * blockDim.x + threadIdx.x;
    if (e < N_EDGES) atomicAdd(&g_deg[rows[e]], 1);
}

__global__ void k_scan() {
    __shared__ int ssum[1024];
    const int t  = threadIdx.x;
    const int CH = (N_NODES + 1023) / 1024;   // 98
    const int start = t * CH;

    int s = 0;
    for (int i = 0; i < CH; i++) {
        int idx = start + i;
        if (idx < N_NODES) s += g_deg[idx];
    }
    ssum[t] = s;
    __syncthreads();
    // Hillis-Steele inclusive scan over 1024 partial sums
    for (int off = 1; off < 1024; off <<= 1) {
        int v = (t >= off) ? ssum[t - off] : 0;
        __syncthreads();
        ssum[t] += v;
        __syncthreads();
    }
    int base = ssum[t] - s;  // exclusive prefix for this chunk
    for (int i = 0; i < CH; i++) {
        int idx = start + i;
        if (idx < N_NODES) {
            g_offs[idx]   = base;
            g_cursor[idx] = base;
            base += g_deg[idx];
        }
    }
    if (t == 1023) g_offs[N_NODES] = ssum[1023];
}

__global__ void k_scatter(const int* __restrict__ rows,
                          const int* __restrict__ cols,
                          const float* __restrict__ vals) {
    int e = blockIdx.x * blockDim.x + threadIdx.x;
    if (e < N_EDGES) {
        int p = atomicAdd(&g_cursor[rows[e]], 1);
        g_csr_col[p] = cols[e];
        g_csr_val[p] = vals[e];
    }
}

// ---------------------------------------------------------------------------
// GEMM: g_h[N,128] = x[N,256] @ W[256,128], fp32
// BM=64, BN=128, BK=16, 256 threads, each thread 8x4 outputs.
// Per warp: trow uniform -> xs reads are broadcast (free); ws float4 reads
// conflict-free.
// ---------------------------------------------------------------------------
__global__ __launch_bounds__(256) void k_gemm(const float* __restrict__ x,
                                              const float* __restrict__ W) {
    __shared__ __align__(16) float xs[64][16];
    __shared__ __align__(16) float ws[16][128];

    const int tid  = threadIdx.x;
    const int trow = tid >> 5;        // 0..7 : 8-row group (uniform per warp)
    const int tcol = tid & 31;        // 0..31: 4-col group
    const int row0 = blockIdx.x * 64;

    float acc[8][4];
    #pragma unroll
    for (int i = 0; i < 8; i++)
        #pragma unroll
        for (int j = 0; j < 4; j++) acc[i][j] = 0.f;

    const int lrow = tid >> 2;        // 0..63  (x tile loader)
    const int lcol = (tid & 3) * 4;   // 0,4,8,12
    const int wrow = tid >> 5;        // 0..7   (W tile loader)
    const int wcol = (tid & 31) * 4;

    for (int kt = 0; kt < F_IN; kt += 16) {
        // load x tile [64x16]
        float4 xv = make_float4(0.f, 0.f, 0.f, 0.f);
        int grow = row0 + lrow;
        if (grow < N_NODES)
            xv = *(const float4*)(x + (size_t)grow * F_IN + kt + lcol);
        *(float4*)&xs[lrow][lcol] = xv;

        // load W tile [16x128]
        *(float4*)&ws[wrow][wcol]     = *(const float4*)(W + (size_t)(kt + wrow)     * F_OUT + wcol);
        *(float4*)&ws[wrow + 8][wcol] = *(const float4*)(W + (size_t)(kt + wrow + 8) * F_OUT + wcol);
        __syncthreads();

        #pragma unroll
        for (int k4 = 0; k4 < 4; k4++) {
            float xr[8][4];
            #pragma unroll
            for (int i = 0; i < 8; i++) {
                float4 t = *(const float4*)&xs[trow * 8 + i][k4 * 4];
                xr[i][0] = t.x; xr[i][1] = t.y; xr[i][2] = t.z; xr[i][3] = t.w;
            }
            float wv[4][4];
            #pragma unroll
            for (int kk = 0; kk < 4; kk++) {
                float4 t = *(const float4*)&ws[k4 * 4 + kk][tcol * 4];
                wv[kk][0] = t.x; wv[kk][1] = t.y; wv[kk][2] = t.z; wv[kk][3] = t.w;
            }
            #pragma unroll
            for (int i = 0; i < 8; i++)
                #pragma unroll
                for (int kk = 0; kk < 4; kk++)
                    #pragma unroll
                    for (int j = 0; j < 4; j++)
                        acc[i][j] = fmaf(xr[i][kk], wv[kk][j], acc[i][j]);
        }
        __syncthreads();
    }

    #pragma unroll
    for (int i = 0; i < 8; i++) {
        int row = row0 + trow * 8 + i;
        if (row < N_NODES) {
            float4 o = make_float4(acc[i][0], acc[i][1], acc[i][2], acc[i][3]);
            *(float4*)(g_h + (size_t)row * F_OUT + tcol * 4) = o;
        }
    }
}

// ---------------------------------------------------------------------------
// SpMM: one warp per output row, register accumulator (lane owns 4 features).
// Edges staged through smem per warp; per edge one coalesced 512B h-row gather
// (L2-resident). No float atomics anywhere.
// ---------------------------------------------------------------------------
__global__ __launch_bounds__(256) void k_spmm(float* __restrict__ out) {
    __shared__ int   s_col[8][32];
    __shared__ float s_val[8][32];

    const int wid  = threadIdx.x >> 5;
    const int lane = threadIdx.x & 31;
    const int r = blockIdx.x * 8 + wid;
    if (r >= N_NODES) return;

    const int start = g_offs[r];
    const int end   = g_offs[r + 1];

    float4 acc = make_float4(0.f, 0.f, 0.f, 0.f);

    for (int base = start; base < end; base += 32) {
        int e = base + lane;
        if (e < end) {
            s_col[wid][lane] = g_csr_col[e];
            s_val[wid][lane] = g_csr_val[e];
        }
        __syncwarp();
        int cnt = min(32, end - base);
        #pragma unroll 4
        for (int j = 0; j < cnt; j++) {
            int   c = s_col[wid][j];
            float v = s_val[wid][j];
            const float4 hv = *(const float4*)(g_h + (size_t)c * F_OUT + lane * 4);
            acc.x = fmaf(v, hv.x, acc.x);
            acc.y = fmaf(v, hv.y, acc.y);
            acc.z = fmaf(v, hv.z, acc.z);
            acc.w = fmaf(v, hv.w, acc.w);
        }
        __syncwarp();
    }

    *(float4*)(out + (size_t)r * F_OUT + lane * 4) = acc;
}

// ---------------------------------------------------------------------------
extern "C" void kernel_launch(void* const* d_in, const int* in_sizes, int n_in,
                              void* d_out, int out_size) {
    const float* x     = (const float*)d_in[0];
    const float* W     = (const float*)d_in[1];
    const float* evals = (const float*)d_in[2];
    const int*   erows = (const int*)d_in[3];
    const int*   ecols = (const int*)d_in[4];
    float*       out   = (float*)d_out;

    k_zero_deg<<<(N_NODES + 255) / 256, 256>>>();
    k_degrees <<<(N_EDGES + 511) / 512, 512>>>(erows);
    k_scan    <<<1, 1024>>>();
    k_scatter <<<(N_EDGES + 511) / 512, 512>>>(erows, ecols, evals);
    k_gemm    <<<(N_NODES + 63) / 64, 256>>>(x, W);
    k_spmm    <<<(N_NODES + 7) / 8, 256>>>(out);
}

// round 9
// speedup vs baseline: 1.2078x; 1.2078x over previous
#include <cuda_runtime.h>
#include <cuda_bf16.h>
#include <cstdint>

#define N_NODES 100000
#define N_EDGES 3200000
#define F_IN    256
#define F_OUT   128

// ---- device scratch (no allocations allowed) ----
__device__ __align__(16) float g_h[N_NODES * F_OUT];          // 51.2 MB projected features
__device__ __align__(16) int2  g_csr[N_EDGES];                // packed (col, val_bits)
__device__ int   g_deg[N_NODES];
__device__ int   g_offs[N_NODES + 1];
__device__ int   g_cursor[N_NODES];
__device__ __align__(16) __nv_bfloat16 g_whT[F_OUT * F_IN];   // W^T hi  [n][k]
__device__ __align__(16) __nv_bfloat16 g_wlT[F_OUT * F_IN];   // W^T lo  [n][k]

// ===========================================================================
// Portable-PTX helpers (mma.sync + ldmatrix — valid at plain sm_103 target)
// ===========================================================================
__device__ __forceinline__ uint32_t smem_u32(const void* p) {
    uint32_t a;
    asm("{ .reg .u64 t; cvta.to.shared.u64 t, %1; cvt.u32.u64 %0, t; }" : "=r"(a) : "l"(p));
    return a;
}
__device__ __forceinline__ void ldmx4(uint32_t* r, uint32_t addr) {
    asm volatile("ldmatrix.sync.aligned.m8n8.x4.shared.b16 {%0,%1,%2,%3}, [%4];"
                 : "=r"(r[0]), "=r"(r[1]), "=r"(r[2]), "=r"(r[3]) : "r"(addr));
}
__device__ __forceinline__ void mma_bf16(float* c, const uint32_t* a, const uint32_t* b) {
    asm volatile("mma.sync.aligned.m16n8k16.row.col.f32.bf16.bf16.f32 "
                 "{%0,%1,%2,%3}, {%4,%5,%6,%7}, {%8,%9}, {%0,%1,%2,%3};"
                 : "+f"(c[0]), "+f"(c[1]), "+f"(c[2]), "+f"(c[3])
                 : "r"(a[0]), "r"(a[1]), "r"(a[2]), "r"(a[3]), "r"(b[0]), "r"(b[1]));
}
__device__ __forceinline__ uint32_t pack2bf(float a, float b) {
    __nv_bfloat162 t = __floats2bfloat162_rn(a, b);
    return *reinterpret_cast<uint32_t*>(&t);
}

// ===========================================================================
// CSR build
// ===========================================================================
__global__ void k_zero_deg() {
    int i = blockIdx.x * blockDim.x + threadIdx.x;
    if (i < N_NODES) g_deg[i] = 0;
}
__global__ void k_degrees(const int* __restrict__ rows) {
    int e = blockIdx.x * blockDim.x + threadIdx.x;
    if (e < N_EDGES) atomicAdd(&g_deg[rows[e]], 1);
}
__global__ void k_scan() {
    __shared__ int ssum[1024];
    const int t = threadIdx.x;
    const int CH = (N_NODES + 1023) / 1024;
    const int start = t * CH;
    int s = 0;
    for (int i = 0; i < CH; i++) {
        int idx = start + i;
        if (idx < N_NODES) s += g_deg[idx];
    }
    ssum[t] = s;
    __syncthreads();
    for (int off = 1; off < 1024; off <<= 1) {
        int v = (t >= off) ? ssum[t - off] : 0;
        __syncthreads();
        ssum[t] += v;
        __syncthreads();
    }
    int base = ssum[t] - s;
    for (int i = 0; i < CH; i++) {
        int idx = start + i;
        if (idx < N_NODES) {
            g_offs[idx] = base;
            g_cursor[idx] = base;
            base += g_deg[idx];
        }
    }
    if (t == 1023) g_offs[N_NODES] = ssum[1023];
}
__global__ void k_scatter(const int* __restrict__ rows, const int* __restrict__ cols,
                          const float* __restrict__ vals) {
    int e = blockIdx.x * blockDim.x + threadIdx.x;
    if (e < N_EDGES) {
        int p = atomicAdd(&g_cursor[rows[e]], 1);
        g_csr[p] = make_int2(cols[e], __float_as_int(vals[e]));
    }
}

// ===========================================================================
// W split+transpose (one-shot, tiny): WhT/WlT [n][k] bf16
// ===========================================================================
__global__ void k_wsplit(const float* __restrict__ W) {
    int k = blockIdx.x;          // 0..255
    int n = threadIdx.x;         // 0..127
    float w = W[k * F_OUT + n];
    __nv_bfloat16 h = __float2bfloat16(w);
    __nv_bfloat16 l = __float2bfloat16(w - __bfloat162float(h));
    g_whT[n * F_IN + k] = h;
    g_wlT[n * F_IN + k] = l;
}

// ===========================================================================
// mma.sync GEMM: g_h[N,128] = x[N,256] @ W  via bf16 hi/lo split (3 terms)
// CTA: 256 thr (8 warps), tile M=128 N=128, K chunks of 64.
// Warp tile 64x32: warps laid out 2(M) x 4(N).
// Smem rows: 64 bf16 = 128 B, SW128 swizzle: off = row*128 + (col2 ^ ((row&7)<<4))
// ===========================================================================
#define KC 64
#define SM_XH 0
#define SM_XL 16384
#define SM_WH 32768
#define SM_WL 49152
#define GEMM_SMEM (65536 + 1024)

__global__ __launch_bounds__(256) void k_gemm_mma(const float* __restrict__ x) {
    extern __shared__ char dsmem[];
    uint32_t raw = smem_u32(dsmem);
    uint32_t base = (raw + 1023u) & ~1023u;     // 1024-align so swizzle bit math holds
    char* sm = dsmem + (base - raw);

    const int tid  = threadIdx.x;
    const int wid  = tid >> 5;
    const int lane = tid & 31;
    const int row0 = blockIdx.x * 128;

    const int wm = (wid & 1) * 64;       // warp M offset
    const int wn = (wid >> 1) * 32;      // warp N offset

    // --- per-lane ldmatrix addressing ---
    // A tiles (x): lanes 0-7: (m0..7, k0), 8-15: (m8..15, k0), 16-23: (m0..7, k8), 24-31: (m8..15, k8)
    const int laneRowA = wm + ((lane >> 3) & 1) * 8 + (lane & 7);
    const uint32_t xmaskA = (uint32_t)((lane & 7) << 4);
    const uint32_t kselA  = (uint32_t)(((lane >> 4) & 1) * 16);   // bytes
    const uint32_t rbA_h  = base + SM_XH + (uint32_t)laneRowA * 128u;
    const uint32_t rbA_l  = base + SM_XL + (uint32_t)laneRowA * 128u;
    // B tiles (W^T): lanes 0-7: (n0..7, k0), 8-15: (n0..7, k8), 16-23: (n8..15, k0), 24-31: (n8..15, k8)
    const int laneRowB = wn + ((lane >> 4) & 1) * 8 + (lane & 7);
    const uint32_t xmaskB = (uint32_t)((lane & 7) << 4);
    const uint32_t kselB  = (uint32_t)(((lane >> 3) & 1) * 16);
    const uint32_t rbB_h  = base + SM_WH + (uint32_t)laneRowB * 128u;
    const uint32_t rbB_l  = base + SM_WL + (uint32_t)laneRowB * 128u;

    float acc[4][4][4];
    #pragma unroll
    for (int i = 0; i < 4; i++)
        #pragma unroll
        for (int j = 0; j < 4; j++)
            #pragma unroll
            for (int q = 0; q < 4; q++) acc[i][j][q] = 0.f;

    for (int kc = 0; kc < F_IN; kc += KC) {
        if (kc) __syncthreads();     // previous chunk's compute done

        // -- stage x chunk: convert fp32 -> bf16 hi/lo, swizzled --
        #pragma unroll
        for (int it = tid; it < 128 * 16; it += 256) {
            int row = it >> 4;
            int col = (it & 15) * 4;
            float4 v = make_float4(0.f, 0.f, 0.f, 0.f);
            int gr = row0 + row;
            if (gr < N_NODES)
                v = *(const float4*)(x + (size_t)gr * F_IN + kc + col);
            float h0 = __bfloat162float(__float2bfloat16(v.x));
            float h1 = __bfloat162float(__float2bfloat16(v.y));
            float h2 = __bfloat162float(__float2bfloat16(v.z));
            float h3 = __bfloat162float(__float2bfloat16(v.w));
            uint32_t off = (uint32_t)row * 128u + (uint32_t)((col * 2) ^ ((row & 7) << 4));
            *(uint2*)(sm + SM_XH + off) = make_uint2(pack2bf(v.x, v.y), pack2bf(v.z, v.w));
            *(uint2*)(sm + SM_XL + off) =
                make_uint2(pack2bf(v.x - h0, v.y - h1), pack2bf(v.z - h2, v.w - h3));
        }
        // -- stage W^T chunk (pre-split bf16), swizzled --
        #pragma unroll
        for (int it = tid; it < 128 * 16; it += 256) {
            int n = it >> 4;
            int c = it & 15;                    // 4-bf16 group
            uint32_t off = (uint32_t)n * 128u + (uint32_t)((c * 8) ^ ((n & 7) << 4));
            *(uint2*)(sm + SM_WH + off) = *(const uint2*)(g_whT + n * F_IN + kc + c * 4);
            *(uint2*)(sm + SM_WL + off) = *(const uint2*)(g_wlT + n * F_IN + kc + c * 4);
        }
        __syncthreads();

        #pragma unroll
        for (int s = 0; s < KC / 16; s++) {
            const uint32_t k2 = (uint32_t)(s * 32);   // k16-step byte offset
            const uint32_t kxA = (k2 + kselA) ^ xmaskA;
            const uint32_t kxB = (k2 + kselB) ^ xmaskB;

            uint32_t bh[8], bl[8];
            ldmx4(bh + 0, rbB_h + kxB);
            ldmx4(bh + 4, rbB_h + 2048u + kxB);
            ldmx4(bl + 0, rbB_l + kxB);
            ldmx4(bl + 4, rbB_l + 2048u + kxB);

            #pragma unroll
            for (int mt = 0; mt < 4; mt++) {
                uint32_t ah[4], al[4];
                ldmx4(ah, rbA_h + (uint32_t)mt * 2048u + kxA);
                ldmx4(al, rbA_l + (uint32_t)mt * 2048u + kxA);
                #pragma unroll
                for (int nt = 0; nt < 4; nt++) {
                    mma_bf16(acc[mt][nt], ah, bh + nt * 2);  // xh * wh
                    mma_bf16(acc[mt][nt], ah, bl + nt * 2);  // xh * wl
                    mma_bf16(acc[mt][nt], al, bh + nt * 2);  // xl * wh
                }
            }
        }
    }

    // -- epilogue: c frag lane mapping g=lane>>2, tg=lane&3 --
    const int g  = lane >> 2;
    const int tg = lane & 3;
    #pragma unroll
    for (int mt = 0; mt < 4; mt++) {
        int m0 = row0 + wm + mt * 16;
        #pragma unroll
        for (int nt = 0; nt < 4; nt++) {
            int n0 = wn + nt * 8 + tg * 2;
            int m = m0 + g;
            if (m < N_NODES)
                *(float2*)(g_h + (size_t)m * F_OUT + n0) =
                    make_float2(acc[mt][nt][0], acc[mt][nt][1]);
            m += 8;
            if (m < N_NODES)
                *(float2*)(g_h + (size_t)m * F_OUT + n0) =
                    make_float2(acc[mt][nt][2], acc[mt][nt][3]);
        }
    }
}

// ===========================================================================
// SpMM: one warp per row; lane owns 4 features; edges staged via smem.
// ===========================================================================
__global__ __launch_bounds__(256) void k_spmm(float* __restrict__ out) {
    __shared__ int2 s_cv[8][32];

    const int wid  = threadIdx.x >> 5;
    const int lane = threadIdx.x & 31;
    const int r = blockIdx.x * 8 + wid;
    if (r >= N_NODES) return;

    const int start = g_offs[r];
    const int end   = g_offs[r + 1];

    float4 acc = make_float4(0.f, 0.f, 0.f, 0.f);

    for (int base = start; base < end; base += 32) {
        int e = base + lane;
        if (e < end) s_cv[wid][lane] = g_csr[e];
        __syncwarp();
        int cnt = min(32, end - base);
        #pragma unroll 8
        for (int j = 0; j < cnt; j++) {
            int2  cv = s_cv[wid][j];
            float v  = __int_as_float(cv.y);
            const float4 hv = *(const float4*)(g_h + (size_t)cv.x * F_OUT + lane * 4);
            acc.x = fmaf(v, hv.x, acc.x);
            acc.y = fmaf(v, hv.y, acc.y);
            acc.z = fmaf(v, hv.z, acc.z);
            acc.w = fmaf(v, hv.w, acc.w);
        }
        __syncwarp();
    }
    *(float4*)(out + (size_t)r * F_OUT + lane * 4) = acc;
}

// ===========================================================================
extern "C" void kernel_launch(void* const* d_in, const int* in_sizes, int n_in,
                              void* d_out, int out_size) {
    const float* x     = (const float*)d_in[0];
    const float* W     = (const float*)d_in[1];
    const float* evals = (const float*)d_in[2];
    const int*   erows = (const int*)d_in[3];
    const int*   ecols = (const int*)d_in[4];
    float*       out   = (float*)d_out;

    cudaFuncSetAttribute(k_gemm_mma, cudaFuncAttributeMaxDynamicSharedMemorySize, GEMM_SMEM);

    k_wsplit  <<<F_IN, F_OUT>>>(W);
    k_zero_deg<<<(N_NODES + 255) / 256, 256>>>();
    k_degrees <<<(N_EDGES + 511) / 512, 512>>>(erows);
    k_scan    <<<1, 1024>>>();
    k_scatter <<<(N_EDGES + 511) / 512, 512>>>(erows, ecols, evals);
    k_gemm_mma<<<(N_NODES + 127) / 128, 256, GEMM_SMEM>>>(x);
    k_spmm    <<<(N_NODES + 7) / 8, 256>>>(out);
}

// round 11
// speedup vs baseline: 1.4841x; 1.2287x over previous
#include <cuda_runtime.h>
#include <cuda_bf16.h>
#include <cstdint>

#define N_NODES 100000
#define N_EDGES 3200000
#define F_IN    256
#define F_OUT   128
#define NBLK    ((N_NODES + 1023) / 1024)   // 98 scan blocks

// ---- device scratch (no allocations allowed) ----
__device__ __align__(16) float g_h[N_NODES * F_OUT];          // 51.2 MB projected features
__device__ __align__(16) int2  g_csr[N_EDGES];                // packed (col, val_bits)
__device__ int   g_deg[N_NODES];
__device__ int   g_offs[N_NODES + 1];
__device__ int   g_cursor[N_NODES];
__device__ int   g_bsum[NBLK];
__device__ int   g_bsumoff[NBLK];
__device__ __align__(16) __nv_bfloat16 g_whT[F_OUT * F_IN];   // W^T hi  [n][k]
__device__ __align__(16) __nv_bfloat16 g_wlT[F_OUT * F_IN];   // W^T lo  [n][k]

// ===========================================================================
// Portable-PTX helpers (mma.sync + ldmatrix — valid at plain sm_103 target)
// ===========================================================================
__device__ __forceinline__ uint32_t smem_u32(const void* p) {
    uint32_t a;
    asm("{ .reg .u64 t; cvta.to.shared.u64 t, %1; cvt.u32.u64 %0, t; }" : "=r"(a) : "l"(p));
    return a;
}
__device__ __forceinline__ void ldmx4(uint32_t* r, uint32_t addr) {
    asm volatile("ldmatrix.sync.aligned.m8n8.x4.shared.b16 {%0,%1,%2,%3}, [%4];"
                 : "=r"(r[0]), "=r"(r[1]), "=r"(r[2]), "=r"(r[3]) : "r"(addr));
}
__device__ __forceinline__ void mma_bf16(float* c, const uint32_t* a, const uint32_t* b) {
    asm volatile("mma.sync.aligned.m16n8k16.row.col.f32.bf16.bf16.f32 "
                 "{%0,%1,%2,%3}, {%4,%5,%6,%7}, {%8,%9}, {%0,%1,%2,%3};"
                 : "+f"(c[0]), "+f"(c[1]), "+f"(c[2]), "+f"(c[3])
                 : "r"(a[0]), "r"(a[1]), "r"(a[2]), "r"(a[3]), "r"(b[0]), "r"(b[1]));
}
__device__ __forceinline__ uint32_t pack2bf(float a, float b) {
    __nv_bfloat162 t = __floats2bfloat162_rn(a, b);
    return *reinterpret_cast<uint32_t*>(&t);
}

// ===========================================================================
// CSR build
// ===========================================================================
__global__ void k_zero_deg() {
    int i = blockIdx.x * blockDim.x + threadIdx.x;
    if (i < N_NODES) g_deg[i] = 0;
}
__global__ void k_degrees(const int* __restrict__ rows) {
    int e = blockIdx.x * blockDim.x + threadIdx.x;
    if (e < N_EDGES) atomicAdd(&g_deg[rows[e]], 1);
}

// ---- parallel scan (3 kernels; replaces the 161us single-block k_scan) ----
__global__ __launch_bounds__(1024) void k_scan_local() {
    __shared__ int warp_tot[32];
    const int t = threadIdx.x;
    const int lane = t & 31, w = t >> 5;
    const int i = blockIdx.x * 1024 + t;
    const int v = (i < N_NODES) ? g_deg[i] : 0;

    // inclusive warp scan
    int s = v;
    #pragma unroll
    for (int off = 1; off < 32; off <<= 1) {
        int u = __shfl_up_sync(0xFFFFFFFFu, s, off);
        if (lane >= off) s += u;
    }
    if (lane == 31) warp_tot[w] = s;
    __syncthreads();
    if (w == 0) {
        int ws = warp_tot[lane];
        #pragma unroll
        for (int off = 1; off < 32; off <<= 1) {
            int u = __shfl_up_sync(0xFFFFFFFFu, ws, off);
            if (lane >= off) ws += u;
        }
        warp_tot[lane] = ws;   // inclusive over warp totals
    }
    __syncthreads();
    const int warp_off = (w > 0) ? warp_tot[w - 1] : 0;
    const int excl = warp_off + s - v;     // block-local exclusive prefix
    if (i < N_NODES) g_offs[i] = excl;
    if (t == 1023) g_bsum[blockIdx.x] = excl + v;   // block total
}

__global__ __launch_bounds__(128) void k_scan_bsum() {
    __shared__ int sh[128];
    const int t = threadIdx.x;
    const int v = (t < NBLK) ? g_bsum[t] : 0;
    sh[t] = v;
    __syncthreads();
    #pragma unroll
    for (int off = 1; off < 128; off <<= 1) {
        int u = (t >= off) ? sh[t - off] : 0;
        __syncthreads();
        sh[t] += u;
        __syncthreads();
    }
    if (t < NBLK) g_bsumoff[t] = sh[t] - v;   // exclusive
    if (t == 127) g_offs[N_NODES] = sh[127];  // grand total
}

__global__ __launch_bounds__(1024) void k_scan_add() {
    const int i = blockIdx.x * 1024 + threadIdx.x;
    if (i < N_NODES) {
        int o = g_offs[i] + g_bsumoff[blockIdx.x];
        g_offs[i] = o;
        g_cursor[i] = o;
    }
}

__global__ void k_scatter(const int* __restrict__ rows, const int* __restrict__ cols,
                          const float* __restrict__ vals) {
    int e = blockIdx.x * blockDim.x + threadIdx.x;
    if (e < N_EDGES) {
        int p = atomicAdd(&g_cursor[rows[e]], 1);
        g_csr[p] = make_int2(cols[e], __float_as_int(vals[e]));
    }
}

// ===========================================================================
// W split+transpose (one-shot, tiny): WhT/WlT [n][k] bf16
// ===========================================================================
__global__ void k_wsplit(const float* __restrict__ W) {
    int k = blockIdx.x;          // 0..255
    int n = threadIdx.x;         // 0..127
    float w = W[k * F_OUT + n];
    __nv_bfloat16 h = __float2bfloat16(w);
    __nv_bfloat16 l = __float2bfloat16(w - __bfloat162float(h));
    g_whT[n * F_IN + k] = h;
    g_wlT[n * F_IN + k] = l;
}

// ===========================================================================
// mma.sync GEMM: g_h[N,128] = x[N,256] @ W  via bf16 hi/lo split (3 terms)
// CTA: 256 thr (8 warps), tile M=128 N=128, K chunks of 64.
// Warp tile 64x32: warps laid out 2(M) x 4(N).
// Smem rows: 64 bf16 = 128 B, SW128 swizzle: off = row*128 + (col2 ^ ((row&7)<<4))
// ===========================================================================
#define KC 64
#define SM_XH 0
#define SM_XL 16384
#define SM_WH 32768
#define SM_WL 49152
#define GEMM_SMEM (65536 + 1024)

__global__ __launch_bounds__(256) void k_gemm_mma(const float* __restrict__ x) {
    extern __shared__ char dsmem[];
    uint32_t raw = smem_u32(dsmem);
    uint32_t base = (raw + 1023u) & ~1023u;     // 1024-align so swizzle bit math holds
    char* sm = dsmem + (base - raw);

    const int tid  = threadIdx.x;
    const int wid  = tid >> 5;
    const int lane = tid & 31;
    const int row0 = blockIdx.x * 128;

    const int wm = (wid & 1) * 64;       // warp M offset
    const int wn = (wid >> 1) * 32;      // warp N offset

    // --- per-lane ldmatrix addressing ---
    const int laneRowA = wm + ((lane >> 3) & 1) * 8 + (lane & 7);
    const uint32_t xmaskA = (uint32_t)((lane & 7) << 4);
    const uint32_t kselA  = (uint32_t)(((lane >> 4) & 1) * 16);   // bytes
    const uint32_t rbA_h  = base + SM_XH + (uint32_t)laneRowA * 128u;
    const uint32_t rbA_l  = base + SM_XL + (uint32_t)laneRowA * 128u;
    const int laneRowB = wn + ((lane >> 4) & 1) * 8 + (lane & 7);
    const uint32_t xmaskB = (uint32_t)((lane & 7) << 4);
    const uint32_t kselB  = (uint32_t)(((lane >> 3) & 1) * 16);
    const uint32_t rbB_h  = base + SM_WH + (uint32_t)laneRowB * 128u;
    const uint32_t rbB_l  = base + SM_WL + (uint32_t)laneRowB * 128u;

    float acc[4][4][4];
    #pragma unroll
    for (int i = 0; i < 4; i++)
        #pragma unroll
        for (int j = 0; j < 4; j++)
            #pragma unroll
            for (int q = 0; q < 4; q++) acc[i][j][q] = 0.f;

    for (int kc = 0; kc < F_IN; kc += KC) {
        if (kc) __syncthreads();     // previous chunk's compute done

        // -- stage x chunk: convert fp32 -> bf16 hi/lo, swizzled --
        #pragma unroll
        for (int it = tid; it < 128 * 16; it += 256) {
            int row = it >> 4;
            int col = (it & 15) * 4;
            float4 v = make_float4(0.f, 0.f, 0.f, 0.f);
            int gr = row0 + row;
            if (gr < N_NODES)
                v = *(const float4*)(x + (size_t)gr * F_IN + kc + col);
            float h0 = __bfloat162float(__float2bfloat16(v.x));
            float h1 = __bfloat162float(__float2bfloat16(v.y));
            float h2 = __bfloat162float(__float2bfloat16(v.z));
            float h3 = __bfloat162float(__float2bfloat16(v.w));
            uint32_t off = (uint32_t)row * 128u + (uint32_t)((col * 2) ^ ((row & 7) << 4));
            *(uint2*)(sm + SM_XH + off) = make_uint2(pack2bf(v.x, v.y), pack2bf(v.z, v.w));
            *(uint2*)(sm + SM_XL + off) =
                make_uint2(pack2bf(v.x - h0, v.y - h1), pack2bf(v.z - h2, v.w - h3));
        }
        // -- stage W^T chunk (pre-split bf16), swizzled --
        #pragma unroll
        for (int it = tid; it < 128 * 16; it += 256) {
            int n = it >> 4;
            int c = it & 15;                    // 4-bf16 group
            uint32_t off = (uint32_t)n * 128u + (uint32_t)((c * 8) ^ ((n & 7) << 4));
            *(uint2*)(sm + SM_WH + off) = *(const uint2*)(g_whT + n * F_IN + kc + c * 4);
            *(uint2*)(sm + SM_WL + off) = *(const uint2*)(g_wlT + n * F_IN + kc + c * 4);
        }
        __syncthreads();

        #pragma unroll
        for (int s = 0; s < KC / 16; s++) {
            const uint32_t k2 = (uint32_t)(s * 32);   // k16-step byte offset
            const uint32_t kxA = (k2 + kselA) ^ xmaskA;
            const uint32_t kxB = (k2 + kselB) ^ xmaskB;

            uint32_t bh[8], bl[8];
            ldmx4(bh + 0, rbB_h + kxB);
            ldmx4(bh + 4, rbB_h + 2048u + kxB);
            ldmx4(bl + 0, rbB_l + kxB);
            ldmx4(bl + 4, rbB_l + 2048u + kxB);

            #pragma unroll
            for (int mt = 0; mt < 4; mt++) {
                uint32_t ah[4], al[4];
                ldmx4(ah, rbA_h + (uint32_t)mt * 2048u + kxA);
                ldmx4(al, rbA_l + (uint32_t)mt * 2048u + kxA);
                #pragma unroll
                for (int nt = 0; nt < 4; nt++) {
                    mma_bf16(acc[mt][nt], ah, bh + nt * 2);  // xh * wh
                    mma_bf16(acc[mt][nt], ah, bl + nt * 2);  // xh * wl
                    mma_bf16(acc[mt][nt], al, bh + nt * 2);  // xl * wh
                }
            }
        }
    }

    // -- epilogue: c frag lane mapping g=lane>>2, tg=lane&3 --
    const int g  = lane >> 2;
    const int tg = lane & 3;
    #pragma unroll
    for (int mt = 0; mt < 4; mt++) {
        int m0 = row0 + wm + mt * 16;
        #pragma unroll
        for (int nt = 0; nt < 4; nt++) {
            int n0 = wn + nt * 8 + tg * 2;
            int m = m0 + g;
            if (m < N_NODES)
                *(float2*)(g_h + (size_t)m * F_OUT + n0) =
                    make_float2(acc[mt][nt][0], acc[mt][nt][1]);
            m += 8;
            if (m < N_NODES)
                *(float2*)(g_h + (size_t)m * F_OUT + n0) =
                    make_float2(acc[mt][nt][2], acc[mt][nt][3]);
        }
    }
}

// ===========================================================================
// SpMM: one warp per row; lane owns 4 features; edges staged via smem.
// ===========================================================================
__global__ __launch_bounds__(256) void k_spmm(float* __restrict__ out) {
    __shared__ int2 s_cv[8][32];

    const int wid  = threadIdx.x >> 5;
    const int lane = threadIdx.x & 31;
    const int r = blockIdx.x * 8 + wid;
    if (r >= N_NODES) return;

    const int start = g_offs[r];
    const int end   = g_offs[r + 1];

    float4 acc = make_float4(0.f, 0.f, 0.f, 0.f);

    for (int base = start; base < end; base += 32) {
        int e = base + lane;
        if (e < end) s_cv[wid][lane] = g_csr[e];
        __syncwarp();
        int cnt = min(32, end - base);
        #pragma unroll 8
        for (int j = 0; j < cnt; j++) {
            int2  cv = s_cv[wid][j];
            float v  = __int_as_float(cv.y);
            const float4 hv = *(const float4*)(g_h + (size_t)cv.x * F_OUT + lane * 4);
            acc.x = fmaf(v, hv.x, acc.x);
            acc.y = fmaf(v, hv.y, acc.y);
            acc.z = fmaf(v, hv.z, acc.z);
            acc.w = fmaf(v, hv.w, acc.w);
        }
        __syncwarp();
    }
    *(float4*)(out + (size_t)r * F_OUT + lane * 4) = acc;
}

// ===========================================================================
extern "C" void kernel_launch(void* const* d_in, const int* in_sizes, int n_in,
                              void* d_out, int out_size) {
    const float* x     = (const float*)d_in[0];
    const float* W     = (const float*)d_in[1];
    const float* evals = (const float*)d_in[2];
    const int*   erows = (const int*)d_in[3];
    const int*   ecols = (const int*)d_in[4];
    float*       out   = (float*)d_out;

    cudaFuncSetAttribute(k_gemm_mma, cudaFuncAttributeMaxDynamicSharedMemorySize, GEMM_SMEM);

    k_wsplit    <<<F_IN, F_OUT>>>(W);
    k_zero_deg  <<<(N_NODES + 255) / 256, 256>>>();
    k_degrees   <<<(N_EDGES + 511) / 512, 512>>>(erows);
    k_scan_local<<<NBLK, 1024>>>();
    k_scan_bsum <<<1, 128>>>();
    k_scan_add  <<<NBLK, 1024>>>();
    k_scatter   <<<(N_EDGES + 511) / 512, 512>>>(erows, ecols, evals);
    k_gemm_mma  <<<(N_NODES + 127) / 128, 256, GEMM_SMEM>>>(x);
    k_spmm      <<<(N_NODES + 7) / 8, 256>>>(out);
}

// round 12
// speedup vs baseline: 2.0704x; 1.3951x over previous
#include <cuda_runtime.h>
#include <cuda_bf16.h>
#include <cuda_fp16.h>
#include <cstdint>

#define N_NODES 100000
#define N_EDGES 3200000
#define F_IN    256
#define F_OUT   128
#define NBLK    ((N_NODES + 1023) / 1024)   // 98 scan blocks

// ---- device scratch (no allocations allowed) ----
__device__ __align__(16) __half2 g_h2[N_NODES * (F_OUT / 2)];  // 25.6 MB projected features (fp16)
__device__ __align__(16) int2  g_csr[N_EDGES];                 // packed (col, val_bits)
__device__ int   g_deg[N_NODES];
__device__ int   g_rank[N_EDGES];
__device__ int   g_offs[N_NODES + 1];
__device__ int   g_bsum[NBLK];
__device__ int   g_bsumoff[NBLK];
__device__ __align__(16) __nv_bfloat16 g_whT[F_OUT * F_IN];    // W^T hi  [n][k]
__device__ __align__(16) __nv_bfloat16 g_wlT[F_OUT * F_IN];    // W^T lo  [n][k]

// ===========================================================================
// Portable-PTX helpers (mma.sync + ldmatrix — valid at plain sm_103 target)
// ===========================================================================
__device__ __forceinline__ uint32_t smem_u32(const void* p) {
    uint32_t a;
    asm("{ .reg .u64 t; cvta.to.shared.u64 t, %1; cvt.u32.u64 %0, t; }" : "=r"(a) : "l"(p));
    return a;
}
__device__ __forceinline__ void ldmx4(uint32_t* r, uint32_t addr) {
    asm volatile("ldmatrix.sync.aligned.m8n8.x4.shared.b16 {%0,%1,%2,%3}, [%4];"
                 : "=r"(r[0]), "=r"(r[1]), "=r"(r[2]), "=r"(r[3]) : "r"(addr));
}
__device__ __forceinline__ void mma_bf16(float* c, const uint32_t* a, const uint32_t* b) {
    asm volatile("mma.sync.aligned.m16n8k16.row.col.f32.bf16.bf16.f32 "
                 "{%0,%1,%2,%3}, {%4,%5,%6,%7}, {%8,%9}, {%0,%1,%2,%3};"
                 : "+f"(c[0]), "+f"(c[1]), "+f"(c[2]), "+f"(c[3])
                 : "r"(a[0]), "r"(a[1]), "r"(a[2]), "r"(a[3]), "r"(b[0]), "r"(b[1]));
}
__device__ __forceinline__ uint32_t pack2bf(float a, float b) {
    __nv_bfloat162 t = __floats2bfloat162_rn(a, b);
    return *reinterpret_cast<uint32_t*>(&t);
}

// ===========================================================================
// CSR build
// ===========================================================================
__global__ void k_zero_deg() {
    int i = blockIdx.x * blockDim.x + threadIdx.x;
    if (i < N_NODES) g_deg[i] = 0;
}
// degrees + per-edge rank (rank removes the need for atomics in scatter)
__global__ void k_degrees(const int* __restrict__ rows) {
    int e = blockIdx.x * blockDim.x + threadIdx.x;
    if (e < N_EDGES) g_rank[e] = atomicAdd(&g_deg[rows[e]], 1);
}

// ---- parallel scan (3 kernels) ----
__global__ __launch_bounds__(1024) void k_scan_local() {
    __shared__ int warp_tot[32];
    const int t = threadIdx.x;
    const int lane = t & 31, w = t >> 5;
    const int i = blockIdx.x * 1024 + t;
    const int v = (i < N_NODES) ? g_deg[i] : 0;

    int s = v;
    #pragma unroll
    for (int off = 1; off < 32; off <<= 1) {
        int u = __shfl_up_sync(0xFFFFFFFFu, s, off);
        if (lane >= off) s += u;
    }
    if (lane == 31) warp_tot[w] = s;
    __syncthreads();
    if (w == 0) {
        int ws = warp_tot[lane];
        #pragma unroll
        for (int off = 1; off < 32; off <<= 1) {
            int u = __shfl_up_sync(0xFFFFFFFFu, ws, off);
            if (lane >= off) ws += u;
        }
        warp_tot[lane] = ws;
    }
    __syncthreads();
    const int warp_off = (w > 0) ? warp_tot[w - 1] : 0;
    const int excl = warp_off + s - v;
    if (i < N_NODES) g_offs[i] = excl;
    if (t == 1023) g_bsum[blockIdx.x] = excl + v;
}

__global__ __launch_bounds__(128) void k_scan_bsum() {
    __shared__ int sh[128];
    const int t = threadIdx.x;
    const int v = (t < NBLK) ? g_bsum[t] : 0;
    sh[t] = v;
    __syncthreads();
    #pragma unroll
    for (int off = 1; off < 128; off <<= 1) {
        int u = (t >= off) ? sh[t - off] : 0;
        __syncthreads();
        sh[t] += u;
        __syncthreads();
    }
    if (t < NBLK) g_bsumoff[t] = sh[t] - v;
    if (t == 127) g_offs[N_NODES] = sh[127];
}

__global__ __launch_bounds__(1024) void k_scan_add() {
    const int i = blockIdx.x * 1024 + threadIdx.x;
    if (i < N_NODES) g_offs[i] += g_bsumoff[blockIdx.x];
}

// atomic-free scatter: slot = offs[row] + rank[e]
__global__ void k_scatter(const int* __restrict__ rows, const int* __restrict__ cols,
                          const float* __restrict__ vals) {
    int e = blockIdx.x * blockDim.x + threadIdx.x;
    if (e < N_EDGES) {
        int p = g_offs[rows[e]] + g_rank[e];
        g_csr[p] = make_int2(cols[e], __float_as_int(vals[e]));
    }
}

// ===========================================================================
// W split+transpose (one-shot, tiny): WhT/WlT [n][k] bf16
// ===========================================================================
__global__ void k_wsplit(const float* __restrict__ W) {
    int k = blockIdx.x;          // 0..255
    int n = threadIdx.x;         // 0..127
    float w = W[k * F_OUT + n];
    __nv_bfloat16 h = __float2bfloat16(w);
    __nv_bfloat16 l = __float2bfloat16(w - __bfloat162float(h));
    g_whT[n * F_IN + k] = h;
    g_wlT[n * F_IN + k] = l;
}

// ===========================================================================
// mma.sync GEMM: h[N,128] = x[N,256] @ W  via bf16 hi/lo split (3 terms)
// Output stored as fp16 (half2 pairs) to halve SpMM gather traffic.
// ===========================================================================
#define KC 64
#define SM_XH 0
#define SM_XL 16384
#define SM_WH 32768
#define SM_WL 49152
#define GEMM_SMEM (65536 + 1024)

__global__ __launch_bounds__(256) void k_gemm_mma(const float* __restrict__ x) {
    extern __shared__ char dsmem[];
    uint32_t raw = smem_u32(dsmem);
    uint32_t base = (raw + 1023u) & ~1023u;
    char* sm = dsmem + (base - raw);

    const int tid  = threadIdx.x;
    const int wid  = tid >> 5;
    const int lane = tid & 31;
    const int row0 = blockIdx.x * 128;

    const int wm = (wid & 1) * 64;
    const int wn = (wid >> 1) * 32;

    const int laneRowA = wm + ((lane >> 3) & 1) * 8 + (lane & 7);
    const uint32_t xmaskA = (uint32_t)((lane & 7) << 4);
    const uint32_t kselA  = (uint32_t)(((lane >> 4) & 1) * 16);
    const uint32_t rbA_h  = base + SM_XH + (uint32_t)laneRowA * 128u;
    const uint32_t rbA_l  = base + SM_XL + (uint32_t)laneRowA * 128u;
    const int laneRowB = wn + ((lane >> 4) & 1) * 8 + (lane & 7);
    const uint32_t xmaskB = (uint32_t)((lane & 7) << 4);
    const uint32_t kselB  = (uint32_t)(((lane >> 3) & 1) * 16);
    const uint32_t rbB_h  = base + SM_WH + (uint32_t)laneRowB * 128u;
    const uint32_t rbB_l  = base + SM_WL + (uint32_t)laneRowB * 128u;

    float acc[4][4][4];
    #pragma unroll
    for (int i = 0; i < 4; i++)
        #pragma unroll
        for (int j = 0; j < 4; j++)
            #pragma unroll
            for (int q = 0; q < 4; q++) acc[i][j][q] = 0.f;

    for (int kc = 0; kc < F_IN; kc += KC) {
        if (kc) __syncthreads();

        #pragma unroll
        for (int it = tid; it < 128 * 16; it += 256) {
            int row = it >> 4;
            int col = (it & 15) * 4;
            float4 v = make_float4(0.f, 0.f, 0.f, 0.f);
            int gr = row0 + row;
            if (gr < N_NODES)
                v = *(const float4*)(x + (size_t)gr * F_IN + kc + col);
            float h0 = __bfloat162float(__float2bfloat16(v.x));
            float h1 = __bfloat162float(__float2bfloat16(v.y));
            float h2 = __bfloat162float(__float2bfloat16(v.z));
            float h3 = __bfloat162float(__float2bfloat16(v.w));
            uint32_t off = (uint32_t)row * 128u + (uint32_t)((col * 2) ^ ((row & 7) << 4));
            *(uint2*)(sm + SM_XH + off) = make_uint2(pack2bf(v.x, v.y), pack2bf(v.z, v.w));
            *(uint2*)(sm + SM_XL + off) =
                make_uint2(pack2bf(v.x - h0, v.y - h1), pack2bf(v.z - h2, v.w - h3));
        }
        #pragma unroll
        for (int it = tid; it < 128 * 16; it += 256) {
            int n = it >> 4;
            int c = it & 15;
            uint32_t off = (uint32_t)n * 128u + (uint32_t)((c * 8) ^ ((n & 7) << 4));
            *(uint2*)(sm + SM_WH + off) = *(const uint2*)(g_whT + n * F_IN + kc + c * 4);
            *(uint2*)(sm + SM_WL + off) = *(const uint2*)(g_wlT + n * F_IN + kc + c * 4);
        }
        __syncthreads();

        #pragma unroll
        for (int s = 0; s < KC / 16; s++) {
            const uint32_t k2 = (uint32_t)(s * 32);
            const uint32_t kxA = (k2 + kselA) ^ xmaskA;
            const uint32_t kxB = (k2 + kselB) ^ xmaskB;

            uint32_t bh[8], bl[8];
            ldmx4(bh + 0, rbB_h + kxB);
            ldmx4(bh + 4, rbB_h + 2048u + kxB);
            ldmx4(bl + 0, rbB_l + kxB);
            ldmx4(bl + 4, rbB_l + 2048u + kxB);

            #pragma unroll
            for (int mt = 0; mt < 4; mt++) {
                uint32_t ah[4], al[4];
                ldmx4(ah, rbA_h + (uint32_t)mt * 2048u + kxA);
                ldmx4(al, rbA_l + (uint32_t)mt * 2048u + kxA);
                #pragma unroll
                for (int nt = 0; nt < 4; nt++) {
                    mma_bf16(acc[mt][nt], ah, bh + nt * 2);  // xh * wh
                    mma_bf16(acc[mt][nt], ah, bl + nt * 2);  // xh * wl
                    mma_bf16(acc[mt][nt], al, bh + nt * 2);  // xl * wh
                }
            }
        }
    }

    // epilogue: store fp16 pairs. n0 always even -> half2 index = (m*128+n0)/2
    const int g  = lane >> 2;
    const int tg = lane & 3;
    #pragma unroll
    for (int mt = 0; mt < 4; mt++) {
        int m0 = row0 + wm + mt * 16;
        #pragma unroll
        for (int nt = 0; nt < 4; nt++) {
            int n0 = wn + nt * 8 + tg * 2;
            int m = m0 + g;
            if (m < N_NODES)
                g_h2[(size_t)m * (F_OUT / 2) + (n0 >> 1)] =
                    __floats2half2_rn(acc[mt][nt][0], acc[mt][nt][1]);
            m += 8;
            if (m < N_NODES)
                g_h2[(size_t)m * (F_OUT / 2) + (n0 >> 1)] =
                    __floats2half2_rn(acc[mt][nt][2], acc[mt][nt][3]);
        }
    }
}

// ===========================================================================
// SpMM: one warp per row; lane owns 4 features (uint2 = 4 fp16); fp32 acc.
// Per edge: 32 lanes x 8B = 256B coalesced gather (halved vs fp32 h).
// ===========================================================================
__global__ __launch_bounds__(256) void k_spmm(float* __restrict__ out) {
    __shared__ int2 s_cv[8][32];

    const int wid  = threadIdx.x >> 5;
    const int lane = threadIdx.x & 31;
    const int r = blockIdx.x * 8 + wid;
    if (r >= N_NODES) return;

    const int start = g_offs[r];
    const int end   = g_offs[r + 1];

    float4 acc = make_float4(0.f, 0.f, 0.f, 0.f);

    for (int base = start; base < end; base += 32) {
        int e = base + lane;
        if (e < end) s_cv[wid][lane] = g_csr[e];
        __syncwarp();
        int cnt = min(32, end - base);
        #pragma unroll 8
        for (int j = 0; j < cnt; j++) {
            int2  cv = s_cv[wid][j];
            float v  = __int_as_float(cv.y);
            const uint2 hv = *((const uint2*)(g_h2 + (size_t)cv.x * (F_OUT / 2)) + lane);
            float2 f01 = __half22float2(*(const __half2*)&hv.x);
            float2 f23 = __half22float2(*(const __half2*)&hv.y);
            acc.x = fmaf(v, f01.x, acc.x);
            acc.y = fmaf(v, f01.y, acc.y);
            acc.z = fmaf(v, f23.x, acc.z);
            acc.w = fmaf(v, f23.y, acc.w);
        }
        __syncwarp();
    }
    *(float4*)(out + (size_t)r * F_OUT + lane * 4) = acc;
}

// ===========================================================================
extern "C" void kernel_launch(void* const* d_in, const int* in_sizes, int n_in,
                              void* d_out, int out_size) {
    const float* x     = (const float*)d_in[0];
    const float* W     = (const float*)d_in[1];
    const float* evals = (const float*)d_in[2];
    const int*   erows = (const int*)d_in[3];
    const int*   ecols = (const int*)d_in[4];
    float*       out   = (float*)d_out;

    cudaFuncSetAttribute(k_gemm_mma, cudaFuncAttributeMaxDynamicSharedMemorySize, GEMM_SMEM);

    k_wsplit    <<<F_IN, F_OUT>>>(W);
    k_zero_deg  <<<(N_NODES + 255) / 256, 256>>>();
    k_degrees   <<<(N_EDGES + 511) / 512, 512>>>(erows);
    k_scan_local<<<NBLK, 1024>>>();
    k_scan_bsum <<<1, 128>>>();
    k_scan_add  <<<NBLK, 1024>>>();
    k_scatter   <<<(N_EDGES + 511) / 512, 512>>>(erows, ecols, evals);
    k_gemm_mma  <<<(N_NODES + 127) / 128, 256, GEMM_SMEM>>>(x);
    k_spmm      <<<(N_NODES + 7) / 8, 256>>>(out);
}